// round 6
// baseline (speedup 1.0000x reference)
#include <cuda_runtime.h>
#include <cuda_bf16.h>
#include <cstdint>
#include <math.h>

#define Hdim 1024
#define Bdim 256
#define Tdim 64
#define Odim 8192
#define MTOT (Tdim*Bdim)
#define NCTA_R 64
#define RSTR 144           // row stride bytes, BK=64 tile row (72 bf16)
#define FSTR 80            // row stride bytes, BK=32 tile row (40 bf16)

typedef __nv_bfloat16 bf16;

// ---------------- scratch ---------------------------------------------------
__device__ __align__(128) bf16 g_Wih_hi[2u*Hdim*Hdim];
__device__ __align__(128) bf16 g_Wih_lo[2u*Hdim*Hdim];
__device__ __align__(128) bf16 g_Whh_hi[2u*Hdim*Hdim];
__device__ __align__(128) bf16 g_Whh_lo[2u*Hdim*Hdim];
__device__ __align__(128) bf16 g_fcW_hi[(size_t)Odim*Hdim];
__device__ __align__(128) bf16 g_fcW_lo[(size_t)Odim*Hdim];
__device__ __align__(128) bf16 g_out_hi[(size_t)MTOT*Hdim];
__device__ __align__(128) bf16 g_out_lo[(size_t)MTOT*Hdim];
__device__ __align__(128) bf16 g_h0_hi[2u*Bdim*Hdim];
__device__ __align__(128) bf16 g_h0_lo[2u*Bdim*Hdim];
__device__ __align__(128) bf16 g_x_hi[Bdim*Hdim];
__device__ __align__(128) bf16 g_x_lo[Bdim*Hdim];
__device__ __align__(128) bf16 g_hid_hi[2u*Bdim*Hdim];
__device__ __align__(128) bf16 g_hid_lo[2u*Bdim*Hdim];

__device__ unsigned g_bar_cnt;
__device__ volatile unsigned g_bar_gen;

// ---------------- helpers ---------------------------------------------------
__device__ __forceinline__ uint32_t smem_u32(const void* p) {
    uint32_t a;
    asm("{ .reg .u64 t; cvta.to.shared.u64 t, %1; cvt.u32.u64 %0, t; }"
        : "=r"(a) : "l"(p));
    return a;
}

__device__ __forceinline__ void ldsm4(uint32_t* r, uint32_t addr) {
    asm volatile("ldmatrix.sync.aligned.m8n8.x4.shared.b16 {%0,%1,%2,%3}, [%4];"
                 : "=r"(r[0]), "=r"(r[1]), "=r"(r[2]), "=r"(r[3]) : "r"(addr));
}

__device__ __forceinline__ void hmma(float* c, const uint32_t* a, const uint32_t* b) {
    asm volatile("mma.sync.aligned.m16n8k16.row.col.f32.bf16.bf16.f32 "
                 "{%0,%1,%2,%3}, {%4,%5,%6,%7}, {%8,%9}, {%0,%1,%2,%3};"
                 : "+f"(c[0]), "+f"(c[1]), "+f"(c[2]), "+f"(c[3])
                 : "r"(a[0]), "r"(a[1]), "r"(a[2]), "r"(a[3]),
                   "r"(b[0]), "r"(b[1]));
}

#define CP_ASYNC16(so, g) \
    asm volatile("cp.async.cg.shared.global [%0], [%1], 16;" :: "r"(so), "l"(g))
#define CP_COMMIT()  asm volatile("cp.async.commit_group;" ::: "memory")
#define CP_WAIT2()   asm volatile("cp.async.wait_group 2;" ::: "memory")
#define CP_WAIT0()   asm volatile("cp.async.wait_group 0;" ::: "memory")

__device__ __forceinline__ void grid_barrier() {
    __syncthreads();
    if (threadIdx.x == 0) {
        __threadfence();
        unsigned gen = g_bar_gen;
        if (atomicAdd(&g_bar_cnt, 1u) == NCTA_R - 1u) {
            atomicExch(&g_bar_cnt, 0u);
            __threadfence();
            g_bar_gen = gen + 1u;
        } else {
            while (g_bar_gen == gen) __nanosleep(32);
        }
    }
    __syncthreads();
}

// ---------------- vectorized split ------------------------------------------
__global__ void split8_kernel(const float4* __restrict__ src,
                              uint4* __restrict__ hi, uint4* __restrict__ lo,
                              int n8) {
    int i = blockIdx.x * blockDim.x + threadIdx.x;
    if (i >= n8) return;
    float4 a = src[2 * i], b = src[2 * i + 1];
    float v[8] = {a.x, a.y, a.z, a.w, b.x, b.y, b.z, b.w};
    __nv_bfloat16 h[8], l[8];
#pragma unroll
    for (int k = 0; k < 8; k++) {
        h[k] = __float2bfloat16(v[k]);
        l[k] = __float2bfloat16(v[k] - __bfloat162float(h[k]));
    }
    uint4 ph, pl;
    ph.x = ((uint32_t)__bfloat16_as_ushort(h[1]) << 16) | __bfloat16_as_ushort(h[0]);
    ph.y = ((uint32_t)__bfloat16_as_ushort(h[3]) << 16) | __bfloat16_as_ushort(h[2]);
    ph.z = ((uint32_t)__bfloat16_as_ushort(h[5]) << 16) | __bfloat16_as_ushort(h[4]);
    ph.w = ((uint32_t)__bfloat16_as_ushort(h[7]) << 16) | __bfloat16_as_ushort(h[6]);
    pl.x = ((uint32_t)__bfloat16_as_ushort(l[1]) << 16) | __bfloat16_as_ushort(l[0]);
    pl.y = ((uint32_t)__bfloat16_as_ushort(l[3]) << 16) | __bfloat16_as_ushort(l[2]);
    pl.z = ((uint32_t)__bfloat16_as_ushort(l[5]) << 16) | __bfloat16_as_ushort(l[4]);
    pl.w = ((uint32_t)__bfloat16_as_ushort(l[7]) << 16) | __bfloat16_as_ushort(l[6]);
    hi[i] = ph;
    lo[i] = pl;
}

// ---------------- persistent RNN --------------------------------------------
// 64 CTAs; BM=64 x BN=64; BK=64; 4-stage cp.async pipeline.
// 8 warps as 2(m) x 4(n): warp tile 32x16, MI=2, NI=2.
__global__ void __launch_bounds__(256) persistent_rnn(
    const bf16* __restrict__ xH,   const bf16* __restrict__ xL,
    const bf16* __restrict__ hidH, const bf16* __restrict__ hidL,
    const bf16* __restrict__ WihH, const bf16* __restrict__ WihL,
    const bf16* __restrict__ WhhH, const bf16* __restrict__ WhhL,
    const float* __restrict__ b_ih, const float* __restrict__ b_hh,
    bf16* __restrict__ outH, bf16* __restrict__ outL,
    bf16* __restrict__ h0H,  bf16* __restrict__ h0L)
{
    constexpr int STAGE = 256 * RSTR;        // 36864 B
    constexpr int offAl = 64 * RSTR;
    constexpr int offBh = 128 * RSTR;
    constexpr int offBl = 192 * RSTR;
    constexpr int BH = Bdim * Hdim;
    constexpr size_t HH = (size_t)Hdim * Hdim;

    extern __shared__ char sm[];
    const uint32_t smb = smem_u32(sm);
    const int tid = threadIdx.x;
    const int wid = tid >> 5, lid = tid & 31;
    const int wm = wid & 1, wn = wid >> 1;
    const int bm = (blockIdx.x & 3) * 64;
    const int bn = (blockIdx.x >> 2) * 64;

#pragma unroll 1
    for (int ph = 0; ph < 2 * Tdim; ++ph) {
        const int t = ph >> 1, layer = ph & 1;

        const bf16 *A0h, *A0l, *A1h, *A1l, *B0h, *B0l, *B1h, *B1l;
        const float *bi0, *bi1;
        bf16 *dH, *dL;
        if (layer == 0) {
            A0h = t ? outH + (size_t)(t - 1) * BH : xH;
            A0l = t ? outL + (size_t)(t - 1) * BH : xL;
            A1h = t ? h0H + (size_t)((t - 1) & 1) * BH : hidH;
            A1l = t ? h0L + (size_t)((t - 1) & 1) * BH : hidL;
            B0h = WihH; B0l = WihL; B1h = WhhH; B1l = WhhL;
            bi0 = b_ih; bi1 = b_hh;
            dH = h0H + (size_t)(t & 1) * BH;
            dL = h0L + (size_t)(t & 1) * BH;
        } else {
            A0h = h0H + (size_t)(t & 1) * BH;
            A0l = h0L + (size_t)(t & 1) * BH;
            A1h = t ? outH + (size_t)(t - 1) * BH : hidH + BH;
            A1l = t ? outL + (size_t)(t - 1) * BH : hidL + BH;
            B0h = WihH + HH; B0l = WihL + HH; B1h = WhhH + HH; B1l = WhhL + HH;
            bi0 = b_ih + Hdim; bi1 = b_hh + Hdim;
            dH = outH + (size_t)t * BH;
            dL = outL + (size_t)t * BH;
        }

        float acc[2][2][4];
#pragma unroll
        for (int mi = 0; mi < 2; mi++)
#pragma unroll
            for (int ni = 0; ni < 2; ni++)
#pragma unroll
                for (int q = 0; q < 4; q++) acc[mi][ni][q] = 0.0f;

        auto load_stage = [&](int it) {
            const bf16* pAh = (it >= 16) ? A1h : A0h;
            const bf16* pAl = (it >= 16) ? A1l : A0l;
            const bf16* pBh = (it >= 16) ? B1h : B0h;
            const bf16* pBl = (it >= 16) ? B1l : B0l;
            const int k0 = (it & 15) * 64;
            const uint32_t sb = smb + (uint32_t)(it & 3) * STAGE;
            // 256 slots x 8 chunks = 2048 x 16B; 8 per thread
#pragma unroll
            for (int rep = 0; rep < 8; rep++) {
                const int idx = rep * 256 + tid;
                const int slot = idx >> 3, c = idx & 7;
                const uint32_t so = sb + slot * RSTR + c * 16;
                const bf16* g;
                if (slot < 64)       g = pAh + (size_t)(bm + slot) * Hdim + k0 + c * 8;
                else if (slot < 128) g = pAl + (size_t)(bm + slot - 64) * Hdim + k0 + c * 8;
                else if (slot < 192) g = pBh + (size_t)(bn + slot - 128) * Hdim + k0 + c * 8;
                else                 g = pBl + (size_t)(bn + slot - 192) * Hdim + k0 + c * 8;
                CP_ASYNC16(so, g);
            }
        };

        load_stage(0); CP_COMMIT();
        load_stage(1); CP_COMMIT();
        load_stage(2); CP_COMMIT();

#pragma unroll 1
        for (int it = 0; it < 32; ++it) {
            CP_WAIT2();
            __syncthreads();
            if (it + 3 < 32) { load_stage(it + 3); CP_COMMIT(); }
            else { CP_COMMIT(); }

            const uint32_t sb = smb + (uint32_t)(it & 3) * STAGE;
#pragma unroll
            for (int kk = 0; kk < 4; kk++) {
                uint32_t ah[2][4], al[2][4];
#pragma unroll
                for (int mi = 0; mi < 2; mi++) {
                    const int row = wm * 32 + mi * 16 + (lid & 15);
                    const int col = kk * 16 + ((lid >> 4) << 3);
                    const uint32_t off = row * RSTR + col * 2;
                    ldsm4(ah[mi], sb + off);
                    ldsm4(al[mi], sb + offAl + off);
                }
                uint32_t bh[2][2], bl[2][2];
                {
                    const int row = wn * 16 + (lid & 7) + ((lid & 16) ? 8 : 0);
                    const int col = kk * 16 + ((lid & 8) ? 8 : 0);
                    const uint32_t off = row * RSTR + col * 2;
                    uint32_t r[4];
                    ldsm4(r, sb + offBh + off);
                    bh[0][0] = r[0]; bh[0][1] = r[1]; bh[1][0] = r[2]; bh[1][1] = r[3];
                    ldsm4(r, sb + offBl + off);
                    bl[0][0] = r[0]; bl[0][1] = r[1]; bl[1][0] = r[2]; bl[1][1] = r[3];
                }
#pragma unroll
                for (int mi = 0; mi < 2; mi++)
#pragma unroll
                    for (int ni = 0; ni < 2; ni++)
                        hmma(acc[mi][ni], ah[mi], bh[ni]);
#pragma unroll
                for (int mi = 0; mi < 2; mi++)
#pragma unroll
                    for (int ni = 0; ni < 2; ni++)
                        hmma(acc[mi][ni], al[mi], bh[ni]);
#pragma unroll
                for (int mi = 0; mi < 2; mi++)
#pragma unroll
                    for (int ni = 0; ni < 2; ni++)
                        hmma(acc[mi][ni], ah[mi], bl[ni]);
            }
        }
        CP_WAIT0();

        // epilogue: bias + tanh + hi/lo split write
#pragma unroll
        for (int mi = 0; mi < 2; mi++) {
#pragma unroll
            for (int ni = 0; ni < 2; ni++) {
                const int r = bm + wm * 32 + mi * 16 + (lid >> 2);
                const int col = bn + wn * 16 + ni * 8 + (lid & 3) * 2;
                const float bv0 = bi0[col] + bi1[col];
                const float bv1 = bi0[col + 1] + bi1[col + 1];
#pragma unroll
                for (int hh2 = 0; hh2 < 2; hh2++) {
                    const int rr = r + hh2 * 8;
                    float v0 = tanhf(acc[mi][ni][2 * hh2 + 0] + bv0);
                    float v1 = tanhf(acc[mi][ni][2 * hh2 + 1] + bv1);
                    bf16 h0v = __float2bfloat16(v0);
                    bf16 h1v = __float2bfloat16(v1);
                    bf16 l0v = __float2bfloat16(v0 - __bfloat162float(h0v));
                    bf16 l1v = __float2bfloat16(v1 - __bfloat162float(h1v));
                    __nv_bfloat162 phv; phv.x = h0v; phv.y = h1v;
                    __nv_bfloat162 plv; plv.x = l0v; plv.y = l1v;
                    *(__nv_bfloat162*)(dH + (size_t)rr * Hdim + col) = phv;
                    *(__nv_bfloat162*)(dL + (size_t)rr * Hdim + col) = plv;
                }
            }
        }

        grid_barrier();
    }
}

// ---------------- fc GEMM: BM=128 BN=128 BK=32, 4-stage ---------------------
// 8 warps as 4(m) x 2(n): warp tile 32x64, MI=2, NI=8, NB=4.
__global__ void __launch_bounds__(256) fc_gemm(
    const bf16* __restrict__ Ah, const bf16* __restrict__ Al,
    const bf16* __restrict__ Bh, const bf16* __restrict__ Bl,
    const float* __restrict__ bias, float* __restrict__ outf)
{
    constexpr int STAGE = 512 * FSTR;        // 40960 B
    constexpr int offAl = 128 * FSTR;
    constexpr int offBh = 256 * FSTR;
    constexpr int offBl = 384 * FSTR;

    extern __shared__ char sm[];
    const uint32_t smb = smem_u32(sm);
    const int tid = threadIdx.x;
    const int wid = tid >> 5, lid = tid & 31;
    const int wm = wid & 3, wn = wid >> 2;
    const int bm = blockIdx.x * 128, bn = blockIdx.y * 128;

    float acc[2][8][4];
#pragma unroll
    for (int mi = 0; mi < 2; mi++)
#pragma unroll
        for (int ni = 0; ni < 8; ni++)
#pragma unroll
            for (int q = 0; q < 4; q++) acc[mi][ni][q] = 0.0f;

    auto load_stage = [&](int it) {
        const int k0 = it * 32;
        const uint32_t sb = smb + (uint32_t)(it & 3) * STAGE;
        // 512 slots x 4 chunks = 2048 x 16B; 8 per thread
#pragma unroll
        for (int rep = 0; rep < 8; rep++) {
            const int idx = rep * 256 + tid;
            const int slot = idx >> 2, c = idx & 3;
            const uint32_t so = sb + slot * FSTR + c * 16;
            const bf16* g;
            if (slot < 128)      g = Ah + (size_t)(bm + slot) * Hdim + k0 + c * 8;
            else if (slot < 256) g = Al + (size_t)(bm + slot - 128) * Hdim + k0 + c * 8;
            else if (slot < 384) g = Bh + (size_t)(bn + slot - 256) * Hdim + k0 + c * 8;
            else                 g = Bl + (size_t)(bn + slot - 384) * Hdim + k0 + c * 8;
            CP_ASYNC16(so, g);
        }
    };

    load_stage(0); CP_COMMIT();
    load_stage(1); CP_COMMIT();
    load_stage(2); CP_COMMIT();

#pragma unroll 1
    for (int it = 0; it < 32; ++it) {
        CP_WAIT2();
        __syncthreads();
        if (it + 3 < 32) { load_stage(it + 3); CP_COMMIT(); }
        else { CP_COMMIT(); }

        const uint32_t sb = smb + (uint32_t)(it & 3) * STAGE;
#pragma unroll
        for (int kk = 0; kk < 2; kk++) {
            uint32_t ah[2][4], al[2][4];
#pragma unroll
            for (int mi = 0; mi < 2; mi++) {
                const int row = wm * 32 + mi * 16 + (lid & 15);
                const int col = kk * 16 + ((lid >> 4) << 3);
                const uint32_t off = row * FSTR + col * 2;
                ldsm4(ah[mi], sb + off);
                ldsm4(al[mi], sb + offAl + off);
            }
            uint32_t bh[8][2], bl[8][2];
#pragma unroll
            for (int nb = 0; nb < 4; nb++) {
                const int row = wn * 64 + nb * 16 + (lid & 7) + ((lid & 16) ? 8 : 0);
                const int col = kk * 16 + ((lid & 8) ? 8 : 0);
                const uint32_t off = row * FSTR + col * 2;
                uint32_t r[4];
                ldsm4(r, sb + offBh + off);
                bh[2 * nb][0] = r[0]; bh[2 * nb][1] = r[1];
                bh[2 * nb + 1][0] = r[2]; bh[2 * nb + 1][1] = r[3];
                ldsm4(r, sb + offBl + off);
                bl[2 * nb][0] = r[0]; bl[2 * nb][1] = r[1];
                bl[2 * nb + 1][0] = r[2]; bl[2 * nb + 1][1] = r[3];
            }
#pragma unroll
            for (int mi = 0; mi < 2; mi++)
#pragma unroll
                for (int ni = 0; ni < 8; ni++)
                    hmma(acc[mi][ni], ah[mi], bh[ni]);
#pragma unroll
            for (int mi = 0; mi < 2; mi++)
#pragma unroll
                for (int ni = 0; ni < 8; ni++)
                    hmma(acc[mi][ni], al[mi], bh[ni]);
#pragma unroll
            for (int mi = 0; mi < 2; mi++)
#pragma unroll
                for (int ni = 0; ni < 8; ni++)
                    hmma(acc[mi][ni], ah[mi], bl[ni]);
        }
    }
    CP_WAIT0();

#pragma unroll
    for (int mi = 0; mi < 2; mi++) {
#pragma unroll
        for (int ni = 0; ni < 8; ni++) {
            const int r = bm + wm * 32 + mi * 16 + (lid >> 2);
            const int col = bn + wn * 64 + ni * 8 + (lid & 3) * 2;
            const float bv0 = bias[col], bv1 = bias[col + 1];
#pragma unroll
            for (int h = 0; h < 2; h++) {
                const int rr = r + h * 8;
                float2 p;
                p.x = acc[mi][ni][2 * h + 0] + bv0;
                p.y = acc[mi][ni][2 * h + 1] + bv1;
                *(float2*)(outf + (size_t)rr * Odim + col) = p;
            }
        }
    }
}

// ---------------- host -------------------------------------------------------
static void split(const float* src, bf16* hi, bf16* lo, int n) {
    int n8 = n / 8;
    split8_kernel<<<(n8 + 255) / 256, 256>>>(
        (const float4*)src, (uint4*)hi, (uint4*)lo, n8);
}

extern "C" void kernel_launch(void* const* d_in, const int* in_sizes, int n_in,
                              void* d_out, int out_size)
{
    const float* x      = (const float*)d_in[0];
    const float* hidden = (const float*)d_in[1];
    const float* W_ih   = (const float*)d_in[3];
    const float* W_hh   = (const float*)d_in[4];
    const float* b_ih   = (const float*)d_in[5];
    const float* b_hh   = (const float*)d_in[6];
    const float* fc_W   = (const float*)d_in[7];
    const float* fc_b   = (const float*)d_in[8];
    float* out = (float*)d_out;

    bf16 *Wih_hi, *Wih_lo, *Whh_hi, *Whh_lo, *fcW_hi, *fcW_lo;
    bf16 *out_hi, *out_lo, *h0_hi, *h0_lo, *x_hi, *x_lo, *hid_hi, *hid_lo;
    cudaGetSymbolAddress((void**)&Wih_hi, g_Wih_hi);
    cudaGetSymbolAddress((void**)&Wih_lo, g_Wih_lo);
    cudaGetSymbolAddress((void**)&Whh_hi, g_Whh_hi);
    cudaGetSymbolAddress((void**)&Whh_lo, g_Whh_lo);
    cudaGetSymbolAddress((void**)&fcW_hi, g_fcW_hi);
    cudaGetSymbolAddress((void**)&fcW_lo, g_fcW_lo);
    cudaGetSymbolAddress((void**)&out_hi, g_out_hi);
    cudaGetSymbolAddress((void**)&out_lo, g_out_lo);
    cudaGetSymbolAddress((void**)&h0_hi, g_h0_hi);
    cudaGetSymbolAddress((void**)&h0_lo, g_h0_lo);
    cudaGetSymbolAddress((void**)&x_hi, g_x_hi);
    cudaGetSymbolAddress((void**)&x_lo, g_x_lo);
    cudaGetSymbolAddress((void**)&hid_hi, g_hid_hi);
    cudaGetSymbolAddress((void**)&hid_lo, g_hid_lo);

    split(W_ih, Wih_hi, Wih_lo, 2 * Hdim * Hdim);
    split(W_hh, Whh_hi, Whh_lo, 2 * Hdim * Hdim);
    split(fc_W, fcW_hi, fcW_lo, Odim * Hdim);
    split(x, x_hi, x_lo, Bdim * Hdim);
    split(hidden, hid_hi, hid_lo, 2 * Bdim * Hdim);

    constexpr int SM_RNN = 4 * 256 * RSTR;   // 147456 B
    constexpr int SM_FC  = 4 * 512 * FSTR;   // 163840 B
    cudaFuncSetAttribute(persistent_rnn,
                         cudaFuncAttributeMaxDynamicSharedMemorySize, SM_RNN);
    cudaFuncSetAttribute(fc_gemm,
                         cudaFuncAttributeMaxDynamicSharedMemorySize, SM_FC);

    persistent_rnn<<<NCTA_R, 256, SM_RNN>>>(
        x_hi, x_lo, hid_hi, hid_lo,
        Wih_hi, Wih_lo, Whh_hi, Whh_lo,
        b_ih, b_hh,
        out_hi, out_lo, h0_hi, h0_lo);

    const dim3 fc_grid(MTOT / 128, Odim / 128);  // (128, 64)
    fc_gemm<<<fc_grid, 256, SM_FC>>>(
        out_hi, out_lo, fcW_hi, fcW_lo, fc_b, out);
}

// round 7
// speedup vs baseline: 1.2691x; 1.2691x over previous
#include <cuda_runtime.h>
#include <cuda_bf16.h>
#include <cstdint>
#include <math.h>

#define Hdim 1024
#define Bdim 256
#define Tdim 64
#define Odim 8192
#define MTOT (Tdim*Bdim)
#define NRNN 128           // RNN worker CTAs (barrier participants)
#define NFC  128           // fc worker CTAs
#define RSTR 144           // row stride bytes, BK=64 tile row
#define FSTR 80            // row stride bytes, BK=32 tile row

typedef __nv_bfloat16 bf16;

// ---------------- scratch ---------------------------------------------------
__device__ __align__(128) bf16 g_Wih_hi[2u*Hdim*Hdim];
__device__ __align__(128) bf16 g_Wih_lo[2u*Hdim*Hdim];
__device__ __align__(128) bf16 g_Whh_hi[2u*Hdim*Hdim];
__device__ __align__(128) bf16 g_Whh_lo[2u*Hdim*Hdim];
__device__ __align__(128) bf16 g_fcW_hi[(size_t)Odim*Hdim];
__device__ __align__(128) bf16 g_fcW_lo[(size_t)Odim*Hdim];
__device__ __align__(128) bf16 g_out_hi[(size_t)MTOT*Hdim];
__device__ __align__(128) bf16 g_out_lo[(size_t)MTOT*Hdim];
__device__ __align__(128) bf16 g_h0_hi[2u*Bdim*Hdim];
__device__ __align__(128) bf16 g_h0_lo[2u*Bdim*Hdim];
__device__ __align__(128) bf16 g_x_hi[Bdim*Hdim];
__device__ __align__(128) bf16 g_x_lo[Bdim*Hdim];
__device__ __align__(128) bf16 g_hid_hi[2u*Bdim*Hdim];
__device__ __align__(128) bf16 g_hid_lo[2u*Bdim*Hdim];

__device__ unsigned g_bar_cnt;
__device__ unsigned g_bar_gen;

// ---------------- helpers ---------------------------------------------------
__device__ __forceinline__ uint32_t smem_u32(const void* p) {
    uint32_t a;
    asm("{ .reg .u64 t; cvta.to.shared.u64 t, %1; cvt.u32.u64 %0, t; }"
        : "=r"(a) : "l"(p));
    return a;
}

__device__ __forceinline__ unsigned ld_acq(unsigned* p) {
    unsigned v;
    asm volatile("ld.acquire.gpu.u32 %0, [%1];" : "=r"(v) : "l"(p));
    return v;
}
__device__ __forceinline__ void st_rel(unsigned* p, unsigned v) {
    asm volatile("st.release.gpu.u32 [%0], %1;" :: "l"(p), "r"(v));
}

__device__ __forceinline__ void ldsm4(uint32_t* r, uint32_t addr) {
    asm volatile("ldmatrix.sync.aligned.m8n8.x4.shared.b16 {%0,%1,%2,%3}, [%4];"
                 : "=r"(r[0]), "=r"(r[1]), "=r"(r[2]), "=r"(r[3]) : "r"(addr));
}

__device__ __forceinline__ void hmma(float* c, const uint32_t* a, const uint32_t* b) {
    asm volatile("mma.sync.aligned.m16n8k16.row.col.f32.bf16.bf16.f32 "
                 "{%0,%1,%2,%3}, {%4,%5,%6,%7}, {%8,%9}, {%0,%1,%2,%3};"
                 : "+f"(c[0]), "+f"(c[1]), "+f"(c[2]), "+f"(c[3])
                 : "r"(a[0]), "r"(a[1]), "r"(a[2]), "r"(a[3]),
                   "r"(b[0]), "r"(b[1]));
}

#define CP_ASYNC16(so, g) \
    asm volatile("cp.async.cg.shared.global [%0], [%1], 16;" :: "r"(so), "l"(g))
#define CP_COMMIT()  asm volatile("cp.async.commit_group;" ::: "memory")
#define CP_WAIT2()   asm volatile("cp.async.wait_group 2;" ::: "memory")
#define CP_WAIT1()   asm volatile("cp.async.wait_group 1;" ::: "memory")
#define CP_WAIT0()   asm volatile("cp.async.wait_group 0;" ::: "memory")

__device__ __forceinline__ void grid_barrier_rnn() {
    __syncthreads();
    if (threadIdx.x == 0) {
        __threadfence();
        unsigned gen = ld_acq(&g_bar_gen);
        if (atomicAdd(&g_bar_cnt, 1u) == NRNN - 1u) {
            atomicExch(&g_bar_cnt, 0u);
            __threadfence();
            st_rel(&g_bar_gen, gen + 1u);
        } else {
            while (ld_acq(&g_bar_gen) == gen) __nanosleep(32);
        }
    }
    __syncthreads();
}

// ---------------- vectorized split ------------------------------------------
__global__ void split8_kernel(const float4* __restrict__ src,
                              uint4* __restrict__ hi, uint4* __restrict__ lo,
                              int n8) {
    int i = blockIdx.x * blockDim.x + threadIdx.x;
    if (i >= n8) return;
    float4 a = src[2 * i], b = src[2 * i + 1];
    float v[8] = {a.x, a.y, a.z, a.w, b.x, b.y, b.z, b.w};
    __nv_bfloat16 h[8], l[8];
#pragma unroll
    for (int k = 0; k < 8; k++) {
        h[k] = __float2bfloat16(v[k]);
        l[k] = __float2bfloat16(v[k] - __bfloat162float(h[k]));
    }
    uint4 ph, pl;
    ph.x = ((uint32_t)__bfloat16_as_ushort(h[1]) << 16) | __bfloat16_as_ushort(h[0]);
    ph.y = ((uint32_t)__bfloat16_as_ushort(h[3]) << 16) | __bfloat16_as_ushort(h[2]);
    ph.z = ((uint32_t)__bfloat16_as_ushort(h[5]) << 16) | __bfloat16_as_ushort(h[4]);
    ph.w = ((uint32_t)__bfloat16_as_ushort(h[7]) << 16) | __bfloat16_as_ushort(h[6]);
    pl.x = ((uint32_t)__bfloat16_as_ushort(l[1]) << 16) | __bfloat16_as_ushort(l[0]);
    pl.y = ((uint32_t)__bfloat16_as_ushort(l[3]) << 16) | __bfloat16_as_ushort(l[2]);
    pl.z = ((uint32_t)__bfloat16_as_ushort(l[5]) << 16) | __bfloat16_as_ushort(l[4]);
    pl.w = ((uint32_t)__bfloat16_as_ushort(l[7]) << 16) | __bfloat16_as_ushort(l[6]);
    hi[i] = ph;
    lo[i] = pl;
}

// ---------------- fused persistent kernel -----------------------------------
// bids [0,128): RNN workers — R5 layout: BM=64 x BN=32, BK=64, 4-stage.
// bids [128,256): fc workers — BM=128 x BN=128, BK=32, 2-stage; worker c does
//   tile (m_tile = 2r + (c>>6), n_tile = c&63) at round r, gated on
//   g_bar_gen >= 2r+2 (out[r] complete).
__global__ void __launch_bounds__(256, 2) fused_kernel(
    const bf16* __restrict__ xH,   const bf16* __restrict__ xL,
    const bf16* __restrict__ hidH, const bf16* __restrict__ hidL,
    const bf16* __restrict__ WihH, const bf16* __restrict__ WihL,
    const bf16* __restrict__ WhhH, const bf16* __restrict__ WhhL,
    const float* __restrict__ b_ih, const float* __restrict__ b_hh,
    const bf16* __restrict__ fcWH, const bf16* __restrict__ fcWL,
    const float* __restrict__ fc_b,
    bf16* __restrict__ outH, bf16* __restrict__ outL,
    bf16* __restrict__ h0H,  bf16* __restrict__ h0L,
    float* __restrict__ logits)
{
    extern __shared__ char sm[];
    const uint32_t smb = smem_u32(sm);
    const int tid = threadIdx.x;
    const int wid = tid >> 5, lid = tid & 31;
    constexpr int BH = Bdim * Hdim;
    constexpr size_t HH = (size_t)Hdim * Hdim;

    if (blockIdx.x < NRNN) {
        // =================== RNN worker ===================
        constexpr int STAGE = 192 * RSTR;
        constexpr int offAl = 64 * RSTR;
        constexpr int offBh = 128 * RSTR;
        constexpr int offBl = 160 * RSTR;
        const int wm = wid & 3, wn = wid >> 2;
        const int bm = (blockIdx.x & 3) * 64;
        const int bn = (blockIdx.x >> 2) * 32;

#pragma unroll 1
        for (int ph = 0; ph < 2 * Tdim; ++ph) {
            const int t = ph >> 1, layer = ph & 1;

            const bf16 *A0h, *A0l, *A1h, *A1l, *B0h, *B0l, *B1h, *B1l;
            const float *bi0, *bi1;
            bf16 *dH, *dL;
            if (layer == 0) {
                A0h = t ? outH + (size_t)(t - 1) * BH : xH;
                A0l = t ? outL + (size_t)(t - 1) * BH : xL;
                A1h = t ? h0H + (size_t)((t - 1) & 1) * BH : hidH;
                A1l = t ? h0L + (size_t)((t - 1) & 1) * BH : hidL;
                B0h = WihH; B0l = WihL; B1h = WhhH; B1l = WhhL;
                bi0 = b_ih; bi1 = b_hh;
                dH = h0H + (size_t)(t & 1) * BH;
                dL = h0L + (size_t)(t & 1) * BH;
            } else {
                A0h = h0H + (size_t)(t & 1) * BH;
                A0l = h0L + (size_t)(t & 1) * BH;
                A1h = t ? outH + (size_t)(t - 1) * BH : hidH + BH;
                A1l = t ? outL + (size_t)(t - 1) * BH : hidL + BH;
                B0h = WihH + HH; B0l = WihL + HH; B1h = WhhH + HH; B1l = WhhL + HH;
                bi0 = b_ih + Hdim; bi1 = b_hh + Hdim;
                dH = outH + (size_t)t * BH;
                dL = outL + (size_t)t * BH;
            }

            float acc[2][4];
#pragma unroll
            for (int ni = 0; ni < 2; ni++)
#pragma unroll
                for (int q = 0; q < 4; q++) acc[ni][q] = 0.0f;

            auto load_stage = [&](int it) {
                const bf16* pAh = (it >= 16) ? A1h : A0h;
                const bf16* pAl = (it >= 16) ? A1l : A0l;
                const bf16* pBh = (it >= 16) ? B1h : B0h;
                const bf16* pBl = (it >= 16) ? B1l : B0l;
                const int k0 = (it & 15) * 64;
                const uint32_t sb = smb + (uint32_t)(it & 3) * STAGE;
#pragma unroll
                for (int rep = 0; rep < 6; rep++) {
                    const int idx = rep * 256 + tid;
                    const int slot = idx >> 3, c = idx & 7;
                    const uint32_t so = sb + slot * RSTR + c * 16;
                    const bf16* g;
                    if (slot < 64)       g = pAh + (size_t)(bm + slot) * Hdim + k0 + c * 8;
                    else if (slot < 128) g = pAl + (size_t)(bm + slot - 64) * Hdim + k0 + c * 8;
                    else if (slot < 160) g = pBh + (size_t)(bn + slot - 128) * Hdim + k0 + c * 8;
                    else                 g = pBl + (size_t)(bn + slot - 160) * Hdim + k0 + c * 8;
                    CP_ASYNC16(so, g);
                }
            };

            load_stage(0); CP_COMMIT();
            load_stage(1); CP_COMMIT();
            load_stage(2); CP_COMMIT();

#pragma unroll 1
            for (int it = 0; it < 32; ++it) {
                CP_WAIT2();
                __syncthreads();
                if (it + 3 < 32) { load_stage(it + 3); CP_COMMIT(); }
                else { CP_COMMIT(); }

                const uint32_t sb = smb + (uint32_t)(it & 3) * STAGE;
#pragma unroll
                for (int kk = 0; kk < 4; kk++) {
                    uint32_t ah[4], al[4];
                    {
                        const int row = wm * 16 + (lid & 15);
                        const int col = kk * 16 + ((lid >> 4) << 3);
                        const uint32_t off = row * RSTR + col * 2;
                        ldsm4(ah, sb + off);
                        ldsm4(al, sb + offAl + off);
                    }
                    uint32_t bh[2][2], bl[2][2];
                    {
                        const int row = wn * 16 + (lid & 7) + ((lid & 16) ? 8 : 0);
                        const int col = kk * 16 + ((lid & 8) ? 8 : 0);
                        const uint32_t off = row * RSTR + col * 2;
                        uint32_t r[4];
                        ldsm4(r, sb + offBh + off);
                        bh[0][0] = r[0]; bh[0][1] = r[1]; bh[1][0] = r[2]; bh[1][1] = r[3];
                        ldsm4(r, sb + offBl + off);
                        bl[0][0] = r[0]; bl[0][1] = r[1]; bl[1][0] = r[2]; bl[1][1] = r[3];
                    }
#pragma unroll
                    for (int ni = 0; ni < 2; ni++) hmma(acc[ni], ah, bh[ni]);
#pragma unroll
                    for (int ni = 0; ni < 2; ni++) hmma(acc[ni], al, bh[ni]);
#pragma unroll
                    for (int ni = 0; ni < 2; ni++) hmma(acc[ni], ah, bl[ni]);
                }
            }
            CP_WAIT0();

#pragma unroll
            for (int ni = 0; ni < 2; ni++) {
                const int r = bm + wm * 16 + (lid >> 2);
                const int col = bn + wn * 16 + ni * 8 + (lid & 3) * 2;
                const float bv0 = bi0[col] + bi1[col];
                const float bv1 = bi0[col + 1] + bi1[col + 1];
#pragma unroll
                for (int hh2 = 0; hh2 < 2; hh2++) {
                    const int rr = r + hh2 * 8;
                    float v0 = tanhf(acc[ni][2 * hh2 + 0] + bv0);
                    float v1 = tanhf(acc[ni][2 * hh2 + 1] + bv1);
                    bf16 h0v = __float2bfloat16(v0);
                    bf16 h1v = __float2bfloat16(v1);
                    bf16 l0v = __float2bfloat16(v0 - __bfloat162float(h0v));
                    bf16 l1v = __float2bfloat16(v1 - __bfloat162float(h1v));
                    __nv_bfloat162 phv; phv.x = h0v; phv.y = h1v;
                    __nv_bfloat162 plv; plv.x = l0v; plv.y = l1v;
                    *(__nv_bfloat162*)(dH + (size_t)rr * Hdim + col) = phv;
                    *(__nv_bfloat162*)(dL + (size_t)rr * Hdim + col) = plv;
                }
            }

            grid_barrier_rnn();
        }
    } else {
        // =================== fc worker ===================
        constexpr int STAGE = 512 * FSTR;      // 40960 B, 2 stages = 81920
        constexpr int offAl = 128 * FSTR;
        constexpr int offBh = 256 * FSTR;
        constexpr int offBl = 384 * FSTR;
        const int c = blockIdx.x - NRNN;       // 0..127
        const int nt = c & 63;                 // n tile 0..63
        const int mh = c >> 6;                 // 0..1
        const int wm = wid & 3, wn = wid >> 2;

#pragma unroll 1
        for (int r = 0; r < Tdim; ++r) {
            // wait until out[r] is fully written (phase 2r+1 done -> gen = 2r+2)
            if (tid == 0) {
                const unsigned tgt = 2u * r + 2u;
                while (ld_acq(&g_bar_gen) < tgt) __nanosleep(256);
            }
            __syncthreads();

            const int bm = r * 256 + mh * 128;
            const int bn = nt * 128;

            float acc[2][8][4];
#pragma unroll
            for (int mi = 0; mi < 2; mi++)
#pragma unroll
                for (int ni = 0; ni < 8; ni++)
#pragma unroll
                    for (int q = 0; q < 4; q++) acc[mi][ni][q] = 0.0f;

            auto load_stage = [&](int it) {
                const int k0 = it * 32;
                const uint32_t sb = smb + (uint32_t)(it & 1) * STAGE;
#pragma unroll
                for (int rep = 0; rep < 8; rep++) {
                    const int idx = rep * 256 + tid;
                    const int slot = idx >> 2, ch = idx & 3;
                    const uint32_t so = sb + slot * FSTR + ch * 16;
                    const bf16* g;
                    if (slot < 128)      g = outH + (size_t)(bm + slot) * Hdim + k0 + ch * 8;
                    else if (slot < 256) g = outL + (size_t)(bm + slot - 128) * Hdim + k0 + ch * 8;
                    else if (slot < 384) g = fcWH + (size_t)(bn + slot - 256) * Hdim + k0 + ch * 8;
                    else                 g = fcWL + (size_t)(bn + slot - 384) * Hdim + k0 + ch * 8;
                    CP_ASYNC16(so, g);
                }
            };

            load_stage(0); CP_COMMIT();

#pragma unroll 1
            for (int it = 0; it < 32; ++it) {
                if (it + 1 < 32) {
                    load_stage(it + 1); CP_COMMIT();
                    CP_WAIT1();
                } else {
                    CP_WAIT0();
                }
                __syncthreads();

                const uint32_t sb = smb + (uint32_t)(it & 1) * STAGE;
#pragma unroll
                for (int kk = 0; kk < 2; kk++) {
                    uint32_t ah[2][4], al[2][4];
#pragma unroll
                    for (int mi = 0; mi < 2; mi++) {
                        const int row = wm * 32 + mi * 16 + (lid & 15);
                        const int col = kk * 16 + ((lid >> 4) << 3);
                        const uint32_t off = row * FSTR + col * 2;
                        ldsm4(ah[mi], sb + off);
                        ldsm4(al[mi], sb + offAl + off);
                    }
                    uint32_t bh[8][2], bl[8][2];
#pragma unroll
                    for (int nb = 0; nb < 4; nb++) {
                        const int row = wn * 64 + nb * 16 + (lid & 7) + ((lid & 16) ? 8 : 0);
                        const int col = kk * 16 + ((lid & 8) ? 8 : 0);
                        const uint32_t off = row * FSTR + col * 2;
                        uint32_t rr[4];
                        ldsm4(rr, sb + offBh + off);
                        bh[2 * nb][0] = rr[0]; bh[2 * nb][1] = rr[1];
                        bh[2 * nb + 1][0] = rr[2]; bh[2 * nb + 1][1] = rr[3];
                        ldsm4(rr, sb + offBl + off);
                        bl[2 * nb][0] = rr[0]; bl[2 * nb][1] = rr[1];
                        bl[2 * nb + 1][0] = rr[2]; bl[2 * nb + 1][1] = rr[3];
                    }
#pragma unroll
                    for (int mi = 0; mi < 2; mi++)
#pragma unroll
                        for (int ni = 0; ni < 8; ni++)
                            hmma(acc[mi][ni], ah[mi], bh[ni]);
#pragma unroll
                    for (int mi = 0; mi < 2; mi++)
#pragma unroll
                        for (int ni = 0; ni < 8; ni++)
                            hmma(acc[mi][ni], al[mi], bh[ni]);
#pragma unroll
                    for (int mi = 0; mi < 2; mi++)
#pragma unroll
                        for (int ni = 0; ni < 8; ni++)
                            hmma(acc[mi][ni], ah[mi], bl[ni]);
                }
                __syncthreads();
            }

#pragma unroll
            for (int mi = 0; mi < 2; mi++) {
#pragma unroll
                for (int ni = 0; ni < 8; ni++) {
                    const int rr = bm + wm * 32 + mi * 16 + (lid >> 2);
                    const int col = bn + wn * 64 + ni * 8 + (lid & 3) * 2;
                    const float bv0 = fc_b[col], bv1 = fc_b[col + 1];
#pragma unroll
                    for (int h = 0; h < 2; h++) {
                        float2 p;
                        p.x = acc[mi][ni][2 * h + 0] + bv0;
                        p.y = acc[mi][ni][2 * h + 1] + bv1;
                        *(float2*)(logits + (size_t)(rr + h * 8) * Odim + col) = p;
                    }
                }
            }
        }
    }
}

// ---------------- host -------------------------------------------------------
static void split(const float* src, bf16* hi, bf16* lo, int n) {
    int n8 = n / 8;
    split8_kernel<<<(n8 + 255) / 256, 256>>>(
        (const float4*)src, (uint4*)hi, (uint4*)lo, n8);
}

extern "C" void kernel_launch(void* const* d_in, const int* in_sizes, int n_in,
                              void* d_out, int out_size)
{
    const float* x      = (const float*)d_in[0];
    const float* hidden = (const float*)d_in[1];
    const float* W_ih   = (const float*)d_in[3];
    const float* W_hh   = (const float*)d_in[4];
    const float* b_ih   = (const float*)d_in[5];
    const float* b_hh   = (const float*)d_in[6];
    const float* fc_W   = (const float*)d_in[7];
    const float* fc_b   = (const float*)d_in[8];
    float* out = (float*)d_out;

    bf16 *Wih_hi, *Wih_lo, *Whh_hi, *Whh_lo, *fcW_hi, *fcW_lo;
    bf16 *out_hi, *out_lo, *h0_hi, *h0_lo, *x_hi, *x_lo, *hid_hi, *hid_lo;
    cudaGetSymbolAddress((void**)&Wih_hi, g_Wih_hi);
    cudaGetSymbolAddress((void**)&Wih_lo, g_Wih_lo);
    cudaGetSymbolAddress((void**)&Whh_hi, g_Whh_hi);
    cudaGetSymbolAddress((void**)&Whh_lo, g_Whh_lo);
    cudaGetSymbolAddress((void**)&fcW_hi, g_fcW_hi);
    cudaGetSymbolAddress((void**)&fcW_lo, g_fcW_lo);
    cudaGetSymbolAddress((void**)&out_hi, g_out_hi);
    cudaGetSymbolAddress((void**)&out_lo, g_out_lo);
    cudaGetSymbolAddress((void**)&h0_hi, g_h0_hi);
    cudaGetSymbolAddress((void**)&h0_lo, g_h0_lo);
    cudaGetSymbolAddress((void**)&x_hi, g_x_hi);
    cudaGetSymbolAddress((void**)&x_lo, g_x_lo);
    cudaGetSymbolAddress((void**)&hid_hi, g_hid_hi);
    cudaGetSymbolAddress((void**)&hid_lo, g_hid_lo);

    split(W_ih, Wih_hi, Wih_lo, 2 * Hdim * Hdim);
    split(W_hh, Whh_hi, Whh_lo, 2 * Hdim * Hdim);
    split(fc_W, fcW_hi, fcW_lo, Odim * Hdim);
    split(x, x_hi, x_lo, Bdim * Hdim);
    split(hidden, hid_hi, hid_lo, 2 * Bdim * Hdim);

    constexpr int SM_FUSED = 4 * 192 * RSTR;   // 110592 B (RNN stages; fc uses 81920)
    cudaFuncSetAttribute(fused_kernel,
                         cudaFuncAttributeMaxDynamicSharedMemorySize, SM_FUSED);

    fused_kernel<<<NRNN + NFC, 256, SM_FUSED>>>(
        x_hi, x_lo, hid_hi, hid_lo,
        Wih_hi, Wih_lo, Whh_hi, Whh_lo,
        b_ih, b_hh,
        fcW_hi, fcW_lo, fc_b,
        out_hi, out_lo, h0_hi, h0_lo,
        out);
}

// round 8
// speedup vs baseline: 1.4906x; 1.1745x over previous
#include <cuda_runtime.h>
#include <cuda_fp16.h>
#include <cstdint>
#include <math.h>

#define Hdim 1024
#define Bdim 256
#define Tdim 64
#define Odim 8192
#define MTOT (Tdim*Bdim)
#define NCTA 128
#define RSTR 144           // row stride bytes for BK=64 tile row (64 half + 16B pad)

typedef __half fp16;

// ---------------- scratch ---------------------------------------------------
__device__ __align__(128) fp16 g_Wih_hi[2u*Hdim*Hdim];
__device__ __align__(128) fp16 g_Wih_lo[2u*Hdim*Hdim];
__device__ __align__(128) fp16 g_Whh_hi[2u*Hdim*Hdim];
__device__ __align__(128) fp16 g_Whh_lo[2u*Hdim*Hdim];
__device__ __align__(128) fp16 g_fcW[(size_t)Odim*Hdim];          // single fp16
__device__ __align__(128) fp16 g_out_hi[(size_t)MTOT*Hdim];
__device__ __align__(128) fp16 g_out_lo[(size_t)MTOT*Hdim];
__device__ __align__(128) fp16 g_h0_hi[2u*Bdim*Hdim];
__device__ __align__(128) fp16 g_h0_lo[2u*Bdim*Hdim];
__device__ __align__(128) fp16 g_x_hi[Bdim*Hdim];
__device__ __align__(128) fp16 g_x_lo[Bdim*Hdim];
__device__ __align__(128) fp16 g_hid_hi[2u*Bdim*Hdim];
__device__ __align__(128) fp16 g_hid_lo[2u*Bdim*Hdim];

__device__ unsigned g_bar_cnt;
__device__ volatile unsigned g_bar_gen;

// ---------------- helpers ---------------------------------------------------
__device__ __forceinline__ uint32_t smem_u32(const void* p) {
    uint32_t a;
    asm("{ .reg .u64 t; cvta.to.shared.u64 t, %1; cvt.u32.u64 %0, t; }"
        : "=r"(a) : "l"(p));
    return a;
}

__device__ __forceinline__ void ldsm4(uint32_t* r, uint32_t addr) {
    asm volatile("ldmatrix.sync.aligned.m8n8.x4.shared.b16 {%0,%1,%2,%3}, [%4];"
                 : "=r"(r[0]), "=r"(r[1]), "=r"(r[2]), "=r"(r[3]) : "r"(addr));
}

__device__ __forceinline__ void hmma(float* c, const uint32_t* a, const uint32_t* b) {
    asm volatile("mma.sync.aligned.m16n8k16.row.col.f32.f16.f16.f32 "
                 "{%0,%1,%2,%3}, {%4,%5,%6,%7}, {%8,%9}, {%0,%1,%2,%3};"
                 : "+f"(c[0]), "+f"(c[1]), "+f"(c[2]), "+f"(c[3])
                 : "r"(a[0]), "r"(a[1]), "r"(a[2]), "r"(a[3]),
                   "r"(b[0]), "r"(b[1]));
}

#define CP_ASYNC16(so, g) \
    asm volatile("cp.async.cg.shared.global [%0], [%1], 16;" :: "r"(so), "l"(g))
#define CP_COMMIT()  asm volatile("cp.async.commit_group;" ::: "memory")
#define CP_WAIT2()   asm volatile("cp.async.wait_group 2;" ::: "memory")
#define CP_WAIT1()   asm volatile("cp.async.wait_group 1;" ::: "memory")
#define CP_WAIT0()   asm volatile("cp.async.wait_group 0;" ::: "memory")

__device__ __forceinline__ void grid_barrier() {
    __syncthreads();
    if (threadIdx.x == 0) {
        __threadfence();
        unsigned gen = g_bar_gen;
        if (atomicAdd(&g_bar_cnt, 1u) == NCTA - 1u) {
            atomicExch(&g_bar_cnt, 0u);
            __threadfence();
            g_bar_gen = gen + 1u;
        } else {
            while (g_bar_gen == gen) __nanosleep(32);
        }
    }
    __syncthreads();
}

// ---------------- fp32 -> (hi, lo) fp16 split, 8 elems/thread ---------------
__global__ void split8_kernel(const float4* __restrict__ src,
                              uint4* __restrict__ hi, uint4* __restrict__ lo,
                              int n8) {
    int i = blockIdx.x * blockDim.x + threadIdx.x;
    if (i >= n8) return;
    float4 a = src[2 * i], b = src[2 * i + 1];
    float v[8] = {a.x, a.y, a.z, a.w, b.x, b.y, b.z, b.w};
    __half h[8], l[8];
#pragma unroll
    for (int k = 0; k < 8; k++) {
        h[k] = __float2half_rn(v[k]);
        l[k] = __float2half_rn(v[k] - __half2float(h[k]));
    }
    uint4 ph, pl;
    ph.x = ((uint32_t)__half_as_ushort(h[1]) << 16) | __half_as_ushort(h[0]);
    ph.y = ((uint32_t)__half_as_ushort(h[3]) << 16) | __half_as_ushort(h[2]);
    ph.z = ((uint32_t)__half_as_ushort(h[5]) << 16) | __half_as_ushort(h[4]);
    ph.w = ((uint32_t)__half_as_ushort(h[7]) << 16) | __half_as_ushort(h[6]);
    pl.x = ((uint32_t)__half_as_ushort(l[1]) << 16) | __half_as_ushort(l[0]);
    pl.y = ((uint32_t)__half_as_ushort(l[3]) << 16) | __half_as_ushort(l[2]);
    pl.z = ((uint32_t)__half_as_ushort(l[5]) << 16) | __half_as_ushort(l[4]);
    pl.w = ((uint32_t)__half_as_ushort(l[7]) << 16) | __half_as_ushort(l[6]);
    hi[i] = ph;
    lo[i] = pl;
}

// ---------------- fp32 -> fp16 convert (no split), 8 elems/thread -----------
__global__ void cvt8_kernel(const float4* __restrict__ src,
                            uint4* __restrict__ dst, int n8) {
    int i = blockIdx.x * blockDim.x + threadIdx.x;
    if (i >= n8) return;
    float4 a = src[2 * i], b = src[2 * i + 1];
    float v[8] = {a.x, a.y, a.z, a.w, b.x, b.y, b.z, b.w};
    __half h[8];
#pragma unroll
    for (int k = 0; k < 8; k++) h[k] = __float2half_rn(v[k]);
    uint4 p;
    p.x = ((uint32_t)__half_as_ushort(h[1]) << 16) | __half_as_ushort(h[0]);
    p.y = ((uint32_t)__half_as_ushort(h[3]) << 16) | __half_as_ushort(h[2]);
    p.z = ((uint32_t)__half_as_ushort(h[5]) << 16) | __half_as_ushort(h[4]);
    p.w = ((uint32_t)__half_as_ushort(h[7]) << 16) | __half_as_ushort(h[6]);
    dst[i] = p;
}

// ---------------- persistent RNN (R5 shape, fp16) ---------------------------
// 128 CTAs; BM=64 x BN=32; BK=64; 4-stage cp.async pipeline; 3 combos.
__global__ void __launch_bounds__(256) persistent_rnn(
    const fp16* __restrict__ xH,   const fp16* __restrict__ xL,
    const fp16* __restrict__ hidH, const fp16* __restrict__ hidL,
    const fp16* __restrict__ WihH, const fp16* __restrict__ WihL,
    const fp16* __restrict__ WhhH, const fp16* __restrict__ WhhL,
    const float* __restrict__ b_ih, const float* __restrict__ b_hh,
    fp16* __restrict__ outH, fp16* __restrict__ outL,
    fp16* __restrict__ h0H,  fp16* __restrict__ h0L)
{
    constexpr int STAGE = 192 * RSTR;
    constexpr int offAl = 64 * RSTR;
    constexpr int offBh = 128 * RSTR;
    constexpr int offBl = 160 * RSTR;
    constexpr int BH = Bdim * Hdim;
    constexpr size_t HH = (size_t)Hdim * Hdim;

    extern __shared__ char sm[];
    const uint32_t smb = smem_u32(sm);
    const int tid = threadIdx.x;
    const int wid = tid >> 5, lid = tid & 31;
    const int wm = wid & 3, wn = wid >> 2;
    const int bm = (blockIdx.x & 3) * 64;
    const int bn = (blockIdx.x >> 2) * 32;

#pragma unroll 1
    for (int ph = 0; ph < 2 * Tdim; ++ph) {
        const int t = ph >> 1, layer = ph & 1;

        const fp16 *A0h, *A0l, *A1h, *A1l, *B0h, *B0l, *B1h, *B1l;
        const float *bi0, *bi1;
        fp16 *dH, *dL;
        if (layer == 0) {
            A0h = t ? outH + (size_t)(t - 1) * BH : xH;
            A0l = t ? outL + (size_t)(t - 1) * BH : xL;
            A1h = t ? h0H + (size_t)((t - 1) & 1) * BH : hidH;
            A1l = t ? h0L + (size_t)((t - 1) & 1) * BH : hidL;
            B0h = WihH; B0l = WihL; B1h = WhhH; B1l = WhhL;
            bi0 = b_ih; bi1 = b_hh;
            dH = h0H + (size_t)(t & 1) * BH;
            dL = h0L + (size_t)(t & 1) * BH;
        } else {
            A0h = h0H + (size_t)(t & 1) * BH;
            A0l = h0L + (size_t)(t & 1) * BH;
            A1h = t ? outH + (size_t)(t - 1) * BH : hidH + BH;
            A1l = t ? outL + (size_t)(t - 1) * BH : hidL + BH;
            B0h = WihH + HH; B0l = WihL + HH; B1h = WhhH + HH; B1l = WhhL + HH;
            bi0 = b_ih + Hdim; bi1 = b_hh + Hdim;
            dH = outH + (size_t)t * BH;
            dL = outL + (size_t)t * BH;
        }

        float acc[2][4];
#pragma unroll
        for (int ni = 0; ni < 2; ni++)
#pragma unroll
            for (int q = 0; q < 4; q++) acc[ni][q] = 0.0f;

        auto load_stage = [&](int it) {
            const fp16* pAh = (it >= 16) ? A1h : A0h;
            const fp16* pAl = (it >= 16) ? A1l : A0l;
            const fp16* pBh = (it >= 16) ? B1h : B0h;
            const fp16* pBl = (it >= 16) ? B1l : B0l;
            const int k0 = (it & 15) * 64;
            const uint32_t sb = smb + (uint32_t)(it & 3) * STAGE;
#pragma unroll
            for (int rep = 0; rep < 6; rep++) {
                const int idx = rep * 256 + tid;
                const int slot = idx >> 3, c = idx & 7;
                const uint32_t so = sb + slot * RSTR + c * 16;
                const fp16* g;
                if (slot < 64)       g = pAh + (size_t)(bm + slot) * Hdim + k0 + c * 8;
                else if (slot < 128) g = pAl + (size_t)(bm + slot - 64) * Hdim + k0 + c * 8;
                else if (slot < 160) g = pBh + (size_t)(bn + slot - 128) * Hdim + k0 + c * 8;
                else                 g = pBl + (size_t)(bn + slot - 160) * Hdim + k0 + c * 8;
                CP_ASYNC16(so, g);
            }
        };

        load_stage(0); CP_COMMIT();
        load_stage(1); CP_COMMIT();
        load_stage(2); CP_COMMIT();

#pragma unroll 1
        for (int it = 0; it < 32; ++it) {
            CP_WAIT2();
            __syncthreads();
            if (it + 3 < 32) { load_stage(it + 3); CP_COMMIT(); }
            else { CP_COMMIT(); }

            const uint32_t sb = smb + (uint32_t)(it & 3) * STAGE;
#pragma unroll
            for (int kk = 0; kk < 4; kk++) {
                uint32_t ah[4], al[4];
                {
                    const int row = wm * 16 + (lid & 15);
                    const int col = kk * 16 + ((lid >> 4) << 3);
                    const uint32_t off = row * RSTR + col * 2;
                    ldsm4(ah, sb + off);
                    ldsm4(al, sb + offAl + off);
                }
                uint32_t bh[2][2], bl[2][2];
                {
                    const int row = wn * 16 + (lid & 7) + ((lid & 16) ? 8 : 0);
                    const int col = kk * 16 + ((lid & 8) ? 8 : 0);
                    const uint32_t off = row * RSTR + col * 2;
                    uint32_t r[4];
                    ldsm4(r, sb + offBh + off);
                    bh[0][0] = r[0]; bh[0][1] = r[1]; bh[1][0] = r[2]; bh[1][1] = r[3];
                    ldsm4(r, sb + offBl + off);
                    bl[0][0] = r[0]; bl[0][1] = r[1]; bl[1][0] = r[2]; bl[1][1] = r[3];
                }
#pragma unroll
                for (int ni = 0; ni < 2; ni++) hmma(acc[ni], ah, bh[ni]);
#pragma unroll
                for (int ni = 0; ni < 2; ni++) hmma(acc[ni], al, bh[ni]);
#pragma unroll
                for (int ni = 0; ni < 2; ni++) hmma(acc[ni], ah, bl[ni]);
            }
        }
        CP_WAIT0();

        // epilogue: bias + tanh + hi/lo fp16 split write
#pragma unroll
        for (int ni = 0; ni < 2; ni++) {
            const int r = bm + wm * 16 + (lid >> 2);
            const int col = bn + wn * 16 + ni * 8 + (lid & 3) * 2;
            const float bv0 = bi0[col] + bi1[col];
            const float bv1 = bi0[col + 1] + bi1[col + 1];
#pragma unroll
            for (int hh2 = 0; hh2 < 2; hh2++) {
                const int rr = r + hh2 * 8;
                float v0 = tanhf(acc[ni][2 * hh2 + 0] + bv0);
                float v1 = tanhf(acc[ni][2 * hh2 + 1] + bv1);
                __half h0v = __float2half_rn(v0);
                __half h1v = __float2half_rn(v1);
                __half l0v = __float2half_rn(v0 - __half2float(h0v));
                __half l1v = __float2half_rn(v1 - __half2float(h1v));
                *(__half2*)(dH + (size_t)rr * Hdim + col) = __halves2half2(h0v, h1v);
                *(__half2*)(dL + (size_t)rr * Hdim + col) = __halves2half2(l0v, l1v);
            }
        }

        grid_barrier();
    }
}

// ---------------- fc GEMM: 2-combo fp16, BM=128 BN=128 BK=64, 3-stage -------
// D = (Ah + Al) @ B^T + bias;  slots: Ah 128 | Al 128 | B 128 = 384.
__global__ void __launch_bounds__(256) fc_gemm(
    const fp16* __restrict__ Ah, const fp16* __restrict__ Al,
    const fp16* __restrict__ B,
    const float* __restrict__ bias, float* __restrict__ outf)
{
    constexpr int STAGE = 384 * RSTR;        // 55296 B
    constexpr int offAl = 128 * RSTR;
    constexpr int offB  = 256 * RSTR;

    extern __shared__ char sm[];
    const uint32_t smb = smem_u32(sm);
    const int tid = threadIdx.x;
    const int wid = tid >> 5, lid = tid & 31;
    const int wm = wid & 3, wn = wid >> 2;
    const int bm = blockIdx.x * 128, bn = blockIdx.y * 128;

    float acc[2][8][4];
#pragma unroll
    for (int mi = 0; mi < 2; mi++)
#pragma unroll
        for (int ni = 0; ni < 8; ni++)
#pragma unroll
            for (int q = 0; q < 4; q++) acc[mi][ni][q] = 0.0f;

    auto load_stage = [&](int it) {
        const int k0 = it * 64;
        const uint32_t sb = smb + (uint32_t)(it % 3) * STAGE;
        // 384 slots x 8 chunks = 3072 x 16B; 12 per thread
#pragma unroll
        for (int rep = 0; rep < 12; rep++) {
            const int idx = rep * 256 + tid;
            const int slot = idx >> 3, c = idx & 7;
            const uint32_t so = sb + slot * RSTR + c * 16;
            const fp16* g;
            if (slot < 128)      g = Ah + (size_t)(bm + slot) * Hdim + k0 + c * 8;
            else if (slot < 256) g = Al + (size_t)(bm + slot - 128) * Hdim + k0 + c * 8;
            else                 g = B + (size_t)(bn + slot - 256) * Hdim + k0 + c * 8;
            CP_ASYNC16(so, g);
        }
    };

    load_stage(0); CP_COMMIT();
    load_stage(1); CP_COMMIT();

#pragma unroll 1
    for (int it = 0; it < 16; ++it) {
        CP_WAIT1();
        __syncthreads();
        if (it + 2 < 16) { load_stage(it + 2); CP_COMMIT(); }
        else { CP_COMMIT(); }

        const uint32_t sb = smb + (uint32_t)(it % 3) * STAGE;
#pragma unroll
        for (int kk = 0; kk < 4; kk++) {
            uint32_t ah[2][4], al[2][4];
#pragma unroll
            for (int mi = 0; mi < 2; mi++) {
                const int row = wm * 32 + mi * 16 + (lid & 15);
                const int col = kk * 16 + ((lid >> 4) << 3);
                const uint32_t off = row * RSTR + col * 2;
                ldsm4(ah[mi], sb + off);
                ldsm4(al[mi], sb + offAl + off);
            }
            uint32_t bh[8][2];
#pragma unroll
            for (int nb = 0; nb < 4; nb++) {
                const int row = wn * 64 + nb * 16 + (lid & 7) + ((lid & 16) ? 8 : 0);
                const int col = kk * 16 + ((lid & 8) ? 8 : 0);
                const uint32_t off = row * RSTR + col * 2;
                uint32_t r[4];
                ldsm4(r, sb + offB + off);
                bh[2 * nb][0] = r[0]; bh[2 * nb][1] = r[1];
                bh[2 * nb + 1][0] = r[2]; bh[2 * nb + 1][1] = r[3];
            }
#pragma unroll
            for (int mi = 0; mi < 2; mi++)
#pragma unroll
                for (int ni = 0; ni < 8; ni++)
                    hmma(acc[mi][ni], ah[mi], bh[ni]);
#pragma unroll
            for (int mi = 0; mi < 2; mi++)
#pragma unroll
                for (int ni = 0; ni < 8; ni++)
                    hmma(acc[mi][ni], al[mi], bh[ni]);
        }
        __syncthreads();
    }
    CP_WAIT0();

#pragma unroll
    for (int mi = 0; mi < 2; mi++) {
#pragma unroll
        for (int ni = 0; ni < 8; ni++) {
            const int r = bm + wm * 32 + mi * 16 + (lid >> 2);
            const int col = bn + wn * 64 + ni * 8 + (lid & 3) * 2;
            const float bv0 = bias[col], bv1 = bias[col + 1];
#pragma unroll
            for (int h = 0; h < 2; h++) {
                const int rr = r + h * 8;
                float2 p;
                p.x = acc[mi][ni][2 * h + 0] + bv0;
                p.y = acc[mi][ni][2 * h + 1] + bv1;
                *(float2*)(outf + (size_t)rr * Odim + col) = p;
            }
        }
    }
}

// ---------------- host -------------------------------------------------------
static void split(const float* src, fp16* hi, fp16* lo, int n) {
    int n8 = n / 8;
    split8_kernel<<<(n8 + 255) / 256, 256>>>(
        (const float4*)src, (uint4*)hi, (uint4*)lo, n8);
}

extern "C" void kernel_launch(void* const* d_in, const int* in_sizes, int n_in,
                              void* d_out, int out_size)
{
    const float* x      = (const float*)d_in[0];
    const float* hidden = (const float*)d_in[1];
    const float* W_ih   = (const float*)d_in[3];
    const float* W_hh   = (const float*)d_in[4];
    const float* b_ih   = (const float*)d_in[5];
    const float* b_hh   = (const float*)d_in[6];
    const float* fc_W   = (const float*)d_in[7];
    const float* fc_b   = (const float*)d_in[8];
    float* out = (float*)d_out;

    fp16 *Wih_hi, *Wih_lo, *Whh_hi, *Whh_lo, *fcW;
    fp16 *out_hi, *out_lo, *h0_hi, *h0_lo, *x_hi, *x_lo, *hid_hi, *hid_lo;
    cudaGetSymbolAddress((void**)&Wih_hi, g_Wih_hi);
    cudaGetSymbolAddress((void**)&Wih_lo, g_Wih_lo);
    cudaGetSymbolAddress((void**)&Whh_hi, g_Whh_hi);
    cudaGetSymbolAddress((void**)&Whh_lo, g_Whh_lo);
    cudaGetSymbolAddress((void**)&fcW, g_fcW);
    cudaGetSymbolAddress((void**)&out_hi, g_out_hi);
    cudaGetSymbolAddress((void**)&out_lo, g_out_lo);
    cudaGetSymbolAddress((void**)&h0_hi, g_h0_hi);
    cudaGetSymbolAddress((void**)&h0_lo, g_h0_lo);
    cudaGetSymbolAddress((void**)&x_hi, g_x_hi);
    cudaGetSymbolAddress((void**)&x_lo, g_x_lo);
    cudaGetSymbolAddress((void**)&hid_hi, g_hid_hi);
    cudaGetSymbolAddress((void**)&hid_lo, g_hid_lo);

    split(W_ih, Wih_hi, Wih_lo, 2 * Hdim * Hdim);
    split(W_hh, Whh_hi, Whh_lo, 2 * Hdim * Hdim);
    {
        int n8 = Odim * Hdim / 8;
        cvt8_kernel<<<(n8 + 255) / 256, 256>>>(
            (const float4*)fc_W, (uint4*)fcW, n8);
    }
    split(x, x_hi, x_lo, Bdim * Hdim);
    split(hidden, hid_hi, hid_lo, 2 * Bdim * Hdim);

    constexpr int SM_RNN = 4 * 192 * RSTR;   // 110592 B
    constexpr int SM_FC  = 3 * 384 * RSTR;   // 165888 B
    cudaFuncSetAttribute(persistent_rnn,
                         cudaFuncAttributeMaxDynamicSharedMemorySize, SM_RNN);
    cudaFuncSetAttribute(fc_gemm,
                         cudaFuncAttributeMaxDynamicSharedMemorySize, SM_FC);

    persistent_rnn<<<NCTA, 256, SM_RNN>>>(
        x_hi, x_lo, hid_hi, hid_lo,
        Wih_hi, Wih_lo, Whh_hi, Whh_lo,
        b_ih, b_hh,
        out_hi, out_lo, h0_hi, h0_lo);

    const dim3 fc_grid(MTOT / 128, Odim / 128);  // (128, 64)
    fc_gemm<<<fc_grid, 256, SM_FC>>>(
        out_hi, out_lo, fcW, fc_b, out);
}

// round 9
// speedup vs baseline: 1.5452x; 1.0367x over previous
#include <cuda_runtime.h>
#include <cuda_fp16.h>
#include <cstdint>
#include <math.h>

#define Hdim 1024
#define Bdim 256
#define Tdim 64
#define Odim 8192
#define MTOT (Tdim*Bdim)
#define NCTA 128
#define RSTR 144           // row stride bytes for BK=64 tile row (64 half + 16B pad)

typedef __half fp16;

// ---------------- scratch ---------------------------------------------------
__device__ __align__(128) fp16 g_Wih_hi[2u*Hdim*Hdim];
__device__ __align__(128) fp16 g_Wih_lo[2u*Hdim*Hdim];
__device__ __align__(128) fp16 g_Whh_hi[2u*Hdim*Hdim];
__device__ __align__(128) fp16 g_Whh_lo[2u*Hdim*Hdim];
__device__ __align__(128) fp16 g_fcW[(size_t)Odim*Hdim];
__device__ __align__(128) fp16 g_out_hi[(size_t)MTOT*Hdim];
__device__ __align__(128) fp16 g_out_lo[(size_t)MTOT*Hdim];
__device__ __align__(128) fp16 g_h0_hi[2u*Bdim*Hdim];
__device__ __align__(128) fp16 g_h0_lo[2u*Bdim*Hdim];
__device__ __align__(128) fp16 g_x_hi[Bdim*Hdim];
__device__ __align__(128) fp16 g_x_lo[Bdim*Hdim];
__device__ __align__(128) fp16 g_hid_hi[2u*Bdim*Hdim];
__device__ __align__(128) fp16 g_hid_lo[2u*Bdim*Hdim];

__device__ unsigned g_flags[NCTA];   // flag-array barrier: flags[b] = iterations completed

// ---------------- helpers ---------------------------------------------------
__device__ __forceinline__ uint32_t smem_u32(const void* p) {
    uint32_t a;
    asm("{ .reg .u64 t; cvta.to.shared.u64 t, %1; cvt.u32.u64 %0, t; }"
        : "=r"(a) : "l"(p));
    return a;
}

__device__ __forceinline__ unsigned ld_acq(const unsigned* p) {
    unsigned v;
    asm volatile("ld.acquire.gpu.u32 %0, [%1];" : "=r"(v) : "l"(p));
    return v;
}
__device__ __forceinline__ void st_rel(unsigned* p, unsigned v) {
    asm volatile("st.release.gpu.u32 [%0], %1;" :: "l"(p), "r"(v));
}

__device__ __forceinline__ void ldsm4(uint32_t* r, uint32_t addr) {
    asm volatile("ldmatrix.sync.aligned.m8n8.x4.shared.b16 {%0,%1,%2,%3}, [%4];"
                 : "=r"(r[0]), "=r"(r[1]), "=r"(r[2]), "=r"(r[3]) : "r"(addr));
}

__device__ __forceinline__ void hmma(float* c, const uint32_t* a, const uint32_t* b) {
    asm volatile("mma.sync.aligned.m16n8k16.row.col.f32.f16.f16.f32 "
                 "{%0,%1,%2,%3}, {%4,%5,%6,%7}, {%8,%9}, {%0,%1,%2,%3};"
                 : "+f"(c[0]), "+f"(c[1]), "+f"(c[2]), "+f"(c[3])
                 : "r"(a[0]), "r"(a[1]), "r"(a[2]), "r"(a[3]),
                   "r"(b[0]), "r"(b[1]));
}

#define CP_ASYNC16(so, g) \
    asm volatile("cp.async.cg.shared.global [%0], [%1], 16;" :: "r"(so), "l"(g))
#define CP_COMMIT()  asm volatile("cp.async.commit_group;" ::: "memory")
#define CP_WAIT2()   asm volatile("cp.async.wait_group 2;" ::: "memory")
#define CP_WAIT1()   asm volatile("cp.async.wait_group 1;" ::: "memory")
#define CP_WAIT0()   asm volatile("cp.async.wait_group 0;" ::: "memory")

// ---------------- splits -----------------------------------------------------
__global__ void split8_kernel(const float4* __restrict__ src,
                              uint4* __restrict__ hi, uint4* __restrict__ lo,
                              int n8) {
    int i = blockIdx.x * blockDim.x + threadIdx.x;
    if (i >= n8) return;
    float4 a = src[2 * i], b = src[2 * i + 1];
    float v[8] = {a.x, a.y, a.z, a.w, b.x, b.y, b.z, b.w};
    __half h[8], l[8];
#pragma unroll
    for (int k = 0; k < 8; k++) {
        h[k] = __float2half_rn(v[k]);
        l[k] = __float2half_rn(v[k] - __half2float(h[k]));
    }
    uint4 ph, pl;
    ph.x = ((uint32_t)__half_as_ushort(h[1]) << 16) | __half_as_ushort(h[0]);
    ph.y = ((uint32_t)__half_as_ushort(h[3]) << 16) | __half_as_ushort(h[2]);
    ph.z = ((uint32_t)__half_as_ushort(h[5]) << 16) | __half_as_ushort(h[4]);
    ph.w = ((uint32_t)__half_as_ushort(h[7]) << 16) | __half_as_ushort(h[6]);
    pl.x = ((uint32_t)__half_as_ushort(l[1]) << 16) | __half_as_ushort(l[0]);
    pl.y = ((uint32_t)__half_as_ushort(l[3]) << 16) | __half_as_ushort(l[2]);
    pl.z = ((uint32_t)__half_as_ushort(l[5]) << 16) | __half_as_ushort(l[4]);
    pl.w = ((uint32_t)__half_as_ushort(l[7]) << 16) | __half_as_ushort(l[6]);
    hi[i] = ph;
    lo[i] = pl;
}

__global__ void cvt8_kernel(const float4* __restrict__ src,
                            uint4* __restrict__ dst, int n8) {
    int i = blockIdx.x * blockDim.x + threadIdx.x;
    if (i >= n8) return;
    float4 a = src[2 * i], b = src[2 * i + 1];
    float v[8] = {a.x, a.y, a.z, a.w, b.x, b.y, b.z, b.w};
    __half h[8];
#pragma unroll
    for (int k = 0; k < 8; k++) h[k] = __float2half_rn(v[k]);
    uint4 p;
    p.x = ((uint32_t)__half_as_ushort(h[1]) << 16) | __half_as_ushort(h[0]);
    p.y = ((uint32_t)__half_as_ushort(h[3]) << 16) | __half_as_ushort(h[2]);
    p.z = ((uint32_t)__half_as_ushort(h[5]) << 16) | __half_as_ushort(h[4]);
    p.w = ((uint32_t)__half_as_ushort(h[7]) << 16) | __half_as_ushort(h[6]);
    dst[i] = p;
}

// ---------------- persistent RNN: dependency-split phases -------------------
// 128 CTAs, BM=64 x BN=32, BK=64, 4-stage pipeline.
// Iteration p (= phase): [indep half: hprev@Whh (input from phase p-2)]
//                        [wait flags >= p]  [dep half: inp@Wih (phase p-1)]
//                        [epilogue] [arrive flags[bid] = p+1]
__global__ void __launch_bounds__(256) persistent_rnn(
    const fp16* __restrict__ xH,   const fp16* __restrict__ xL,
    const fp16* __restrict__ hidH, const fp16* __restrict__ hidL,
    const fp16* __restrict__ WihH, const fp16* __restrict__ WihL,
    const fp16* __restrict__ WhhH, const fp16* __restrict__ WhhL,
    const float* __restrict__ b_ih, const float* __restrict__ b_hh,
    fp16* __restrict__ outH, fp16* __restrict__ outL,
    fp16* __restrict__ h0H,  fp16* __restrict__ h0L)
{
    constexpr int STAGE = 192 * RSTR;
    constexpr int offAl = 64 * RSTR;
    constexpr int offBh = 128 * RSTR;
    constexpr int offBl = 160 * RSTR;
    constexpr int BH = Bdim * Hdim;
    constexpr size_t HH = (size_t)Hdim * Hdim;

    extern __shared__ char sm[];
    const uint32_t smb = smem_u32(sm);
    const int tid = threadIdx.x;
    const int wid = tid >> 5, lid = tid & 31;
    const int wm = wid & 3, wn = wid >> 2;
    const int bm = (blockIdx.x & 3) * 64;
    const int bn = (blockIdx.x >> 2) * 32;

    float acc[2][4];

    // one K=1024 half-GEMM: acc += A@B^T, 16 iters, 4-stage pipeline
    auto run_half = [&](const fp16* pAh, const fp16* pAl,
                        const fp16* pBh, const fp16* pBl) {
        auto load_stage = [&](int it) {
            const int k0 = it * 64;
            const uint32_t sb = smb + (uint32_t)(it & 3) * STAGE;
#pragma unroll
            for (int rep = 0; rep < 6; rep++) {
                const int idx = rep * 256 + tid;
                const int slot = idx >> 3, c = idx & 7;
                const uint32_t so = sb + slot * RSTR + c * 16;
                const fp16* g;
                if (slot < 64)       g = pAh + (size_t)(bm + slot) * Hdim + k0 + c * 8;
                else if (slot < 128) g = pAl + (size_t)(bm + slot - 64) * Hdim + k0 + c * 8;
                else if (slot < 160) g = pBh + (size_t)(bn + slot - 128) * Hdim + k0 + c * 8;
                else                 g = pBl + (size_t)(bn + slot - 160) * Hdim + k0 + c * 8;
                CP_ASYNC16(so, g);
            }
        };

        load_stage(0); CP_COMMIT();
        load_stage(1); CP_COMMIT();
        load_stage(2); CP_COMMIT();

#pragma unroll 1
        for (int it = 0; it < 16; ++it) {
            CP_WAIT2();
            __syncthreads();
            if (it + 3 < 16) { load_stage(it + 3); CP_COMMIT(); }
            else { CP_COMMIT(); }   // keep group count consistent

            const uint32_t sb = smb + (uint32_t)(it & 3) * STAGE;
#pragma unroll
            for (int kk = 0; kk < 4; kk++) {
                uint32_t ah[4], al[4];
                {
                    const int row = wm * 16 + (lid & 15);
                    const int col = kk * 16 + ((lid >> 4) << 3);
                    const uint32_t off = row * RSTR + col * 2;
                    ldsm4(ah, sb + off);
                    ldsm4(al, sb + offAl + off);
                }
                uint32_t bh[2][2], bl[2][2];
                {
                    const int row = wn * 16 + (lid & 7) + ((lid & 16) ? 8 : 0);
                    const int col = kk * 16 + ((lid & 8) ? 8 : 0);
                    const uint32_t off = row * RSTR + col * 2;
                    uint32_t r[4];
                    ldsm4(r, sb + offBh + off);
                    bh[0][0] = r[0]; bh[0][1] = r[1]; bh[1][0] = r[2]; bh[1][1] = r[3];
                    ldsm4(r, sb + offBl + off);
                    bl[0][0] = r[0]; bl[0][1] = r[1]; bl[1][0] = r[2]; bl[1][1] = r[3];
                }
#pragma unroll
                for (int ni = 0; ni < 2; ni++) hmma(acc[ni], ah, bh[ni]);
#pragma unroll
                for (int ni = 0; ni < 2; ni++) hmma(acc[ni], al, bh[ni]);
#pragma unroll
                for (int ni = 0; ni < 2; ni++) hmma(acc[ni], ah, bl[ni]);
            }
        }
        CP_WAIT0();
        __syncthreads();
    };

#pragma unroll 1
    for (int p = 0; p < 2 * Tdim; ++p) {
        const int t = p >> 1, layer = p & 1;

        // indep operand (from phase p-2 / initial inputs)
        const fp16 *Aih, *Ail;
        if (layer == 0) {
            Aih = t ? h0H + (size_t)((t - 1) & 1) * BH : hidH;
            Ail = t ? h0L + (size_t)((t - 1) & 1) * BH : hidL;
        } else {
            Aih = t ? outH + (size_t)(t - 1) * BH : hidH + BH;
            Ail = t ? outL + (size_t)(t - 1) * BH : hidL + BH;
        }
        const fp16* Bih_ = WhhH + layer * HH;
        const fp16* Bil_ = WhhL + layer * HH;

        // dep operand (from phase p-1 / x)
        const fp16 *Adh, *Adl;
        if (layer == 0) {
            Adh = t ? outH + (size_t)(t - 1) * BH : xH;
            Adl = t ? outL + (size_t)(t - 1) * BH : xL;
        } else {
            Adh = h0H + (size_t)(t & 1) * BH;
            Adl = h0L + (size_t)(t & 1) * BH;
        }
        const fp16* Bdh_ = WihH + layer * HH;
        const fp16* Bdl_ = WihL + layer * HH;

        const float* bi0 = b_ih + layer * Hdim;
        const float* bi1 = b_hh + layer * Hdim;
        fp16* dH = (layer == 0) ? h0H + (size_t)(t & 1) * BH : outH + (size_t)t * BH;
        fp16* dL = (layer == 0) ? h0L + (size_t)(t & 1) * BH : outL + (size_t)t * BH;

#pragma unroll
        for (int ni = 0; ni < 2; ni++)
#pragma unroll
            for (int q = 0; q < 4; q++) acc[ni][q] = 0.0f;

        // 1) independent half — no wait needed (covered by wait in iteration p-1)
        run_half(Aih, Ail, Bih_, Bil_);

        // 2) wait for phase p-1 completion (flags[b] >= p for all b)
        {
            const unsigned tgt = (unsigned)p;
            for (;;) {
                unsigned v = ld_acq(&g_flags[tid & (NCTA - 1)]);
                if (__syncthreads_and(v >= tgt)) break;
            }
        }

        // 3) dependent half
        run_half(Adh, Adl, Bdh_, Bdl_);

        // 4) epilogue: bias + tanh + hi/lo split write
#pragma unroll
        for (int ni = 0; ni < 2; ni++) {
            const int r = bm + wm * 16 + (lid >> 2);
            const int col = bn + wn * 16 + ni * 8 + (lid & 3) * 2;
            const float bv0 = bi0[col] + bi1[col];
            const float bv1 = bi0[col + 1] + bi1[col + 1];
#pragma unroll
            for (int hh2 = 0; hh2 < 2; hh2++) {
                const int rr = r + hh2 * 8;
                float v0 = tanhf(acc[ni][2 * hh2 + 0] + bv0);
                float v1 = tanhf(acc[ni][2 * hh2 + 1] + bv1);
                __half h0v = __float2half_rn(v0);
                __half h1v = __float2half_rn(v1);
                __half l0v = __float2half_rn(v0 - __half2float(h0v));
                __half l1v = __float2half_rn(v1 - __half2float(h1v));
                *(__half2*)(dH + (size_t)rr * Hdim + col) = __halves2half2(h0v, h1v);
                *(__half2*)(dL + (size_t)rr * Hdim + col) = __halves2half2(l0v, l1v);
            }
        }

        // 5) arrive
        __syncthreads();
        if (tid == 0) {
            __threadfence();
            st_rel(&g_flags[blockIdx.x], (unsigned)(p + 1));
        }
    }

    // reset flags for next graph replay (deterministic re-entry)
    __syncthreads();
    if (tid == 0) st_rel(&g_flags[blockIdx.x], 0u);
}

// ---------------- fc GEMM: 2-combo fp16, BM=128 BN=128 BK=64, 3-stage -------
__global__ void __launch_bounds__(256) fc_gemm(
    const fp16* __restrict__ Ah, const fp16* __restrict__ Al,
    const fp16* __restrict__ B,
    const float* __restrict__ bias, float* __restrict__ outf)
{
    constexpr int STAGE = 384 * RSTR;
    constexpr int offAl = 128 * RSTR;
    constexpr int offB  = 256 * RSTR;

    extern __shared__ char sm[];
    const uint32_t smb = smem_u32(sm);
    const int tid = threadIdx.x;
    const int wid = tid >> 5, lid = tid & 31;
    const int wm = wid & 3, wn = wid >> 2;
    const int bm = blockIdx.x * 128, bn = blockIdx.y * 128;

    float acc[2][8][4];
#pragma unroll
    for (int mi = 0; mi < 2; mi++)
#pragma unroll
        for (int ni = 0; ni < 8; ni++)
#pragma unroll
            for (int q = 0; q < 4; q++) acc[mi][ni][q] = 0.0f;

    auto load_stage = [&](int it) {
        const int k0 = it * 64;
        const uint32_t sb = smb + (uint32_t)(it % 3) * STAGE;
#pragma unroll
        for (int rep = 0; rep < 12; rep++) {
            const int idx = rep * 256 + tid;
            const int slot = idx >> 3, c = idx & 7;
            const uint32_t so = sb + slot * RSTR + c * 16;
            const fp16* g;
            if (slot < 128)      g = Ah + (size_t)(bm + slot) * Hdim + k0 + c * 8;
            else if (slot < 256) g = Al + (size_t)(bm + slot - 128) * Hdim + k0 + c * 8;
            else                 g = B + (size_t)(bn + slot - 256) * Hdim + k0 + c * 8;
            CP_ASYNC16(so, g);
        }
    };

    load_stage(0); CP_COMMIT();
    load_stage(1); CP_COMMIT();

#pragma unroll 1
    for (int it = 0; it < 16; ++it) {
        CP_WAIT1();
        __syncthreads();
        if (it + 2 < 16) { load_stage(it + 2); CP_COMMIT(); }
        else { CP_COMMIT(); }

        const uint32_t sb = smb + (uint32_t)(it % 3) * STAGE;
#pragma unroll
        for (int kk = 0; kk < 4; kk++) {
            uint32_t ah[2][4], al[2][4];
#pragma unroll
            for (int mi = 0; mi < 2; mi++) {
                const int row = wm * 32 + mi * 16 + (lid & 15);
                const int col = kk * 16 + ((lid >> 4) << 3);
                const uint32_t off = row * RSTR + col * 2;
                ldsm4(ah[mi], sb + off);
                ldsm4(al[mi], sb + offAl + off);
            }
            uint32_t bh[8][2];
#pragma unroll
            for (int nb = 0; nb < 4; nb++) {
                const int row = wn * 64 + nb * 16 + (lid & 7) + ((lid & 16) ? 8 : 0);
                const int col = kk * 16 + ((lid & 8) ? 8 : 0);
                const uint32_t off = row * RSTR + col * 2;
                uint32_t r[4];
                ldsm4(r, sb + offB + off);
                bh[2 * nb][0] = r[0]; bh[2 * nb][1] = r[1];
                bh[2 * nb + 1][0] = r[2]; bh[2 * nb + 1][1] = r[3];
            }
#pragma unroll
            for (int mi = 0; mi < 2; mi++)
#pragma unroll
                for (int ni = 0; ni < 8; ni++)
                    hmma(acc[mi][ni], ah[mi], bh[ni]);
#pragma unroll
            for (int mi = 0; mi < 2; mi++)
#pragma unroll
                for (int ni = 0; ni < 8; ni++)
                    hmma(acc[mi][ni], al[mi], bh[ni]);
        }
        __syncthreads();
    }
    CP_WAIT0();

#pragma unroll
    for (int mi = 0; mi < 2; mi++) {
#pragma unroll
        for (int ni = 0; ni < 8; ni++) {
            const int r = bm + wm * 32 + mi * 16 + (lid >> 2);
            const int col = bn + wn * 64 + ni * 8 + (lid & 3) * 2;
            const float bv0 = bias[col], bv1 = bias[col + 1];
#pragma unroll
            for (int h = 0; h < 2; h++) {
                const int rr = r + h * 8;
                float2 p;
                p.x = acc[mi][ni][2 * h + 0] + bv0;
                p.y = acc[mi][ni][2 * h + 1] + bv1;
                *(float2*)(outf + (size_t)rr * Odim + col) = p;
            }
        }
    }
}

// ---------------- host -------------------------------------------------------
static void split(const float* src, fp16* hi, fp16* lo, int n) {
    int n8 = n / 8;
    split8_kernel<<<(n8 + 255) / 256, 256>>>(
        (const float4*)src, (uint4*)hi, (uint4*)lo, n8);
}

extern "C" void kernel_launch(void* const* d_in, const int* in_sizes, int n_in,
                              void* d_out, int out_size)
{
    const float* x      = (const float*)d_in[0];
    const float* hidden = (const float*)d_in[1];
    const float* W_ih   = (const float*)d_in[3];
    const float* W_hh   = (const float*)d_in[4];
    const float* b_ih   = (const float*)d_in[5];
    const float* b_hh   = (const float*)d_in[6];
    const float* fc_W   = (const float*)d_in[7];
    const float* fc_b   = (const float*)d_in[8];
    float* out = (float*)d_out;

    fp16 *Wih_hi, *Wih_lo, *Whh_hi, *Whh_lo, *fcW;
    fp16 *out_hi, *out_lo, *h0_hi, *h0_lo, *x_hi, *x_lo, *hid_hi, *hid_lo;
    cudaGetSymbolAddress((void**)&Wih_hi, g_Wih_hi);
    cudaGetSymbolAddress((void**)&Wih_lo, g_Wih_lo);
    cudaGetSymbolAddress((void**)&Whh_hi, g_Whh_hi);
    cudaGetSymbolAddress((void**)&Whh_lo, g_Whh_lo);
    cudaGetSymbolAddress((void**)&fcW, g_fcW);
    cudaGetSymbolAddress((void**)&out_hi, g_out_hi);
    cudaGetSymbolAddress((void**)&out_lo, g_out_lo);
    cudaGetSymbolAddress((void**)&h0_hi, g_h0_hi);
    cudaGetSymbolAddress((void**)&h0_lo, g_h0_lo);
    cudaGetSymbolAddress((void**)&x_hi, g_x_hi);
    cudaGetSymbolAddress((void**)&x_lo, g_x_lo);
    cudaGetSymbolAddress((void**)&hid_hi, g_hid_hi);
    cudaGetSymbolAddress((void**)&hid_lo, g_hid_lo);

    split(W_ih, Wih_hi, Wih_lo, 2 * Hdim * Hdim);
    split(W_hh, Whh_hi, Whh_lo, 2 * Hdim * Hdim);
    {
        int n8 = Odim * Hdim / 8;
        cvt8_kernel<<<(n8 + 255) / 256, 256>>>(
            (const float4*)fc_W, (uint4*)fcW, n8);
    }
    split(x, x_hi, x_lo, Bdim * Hdim);
    split(hidden, hid_hi, hid_lo, 2 * Bdim * Hdim);

    constexpr int SM_RNN = 4 * 192 * RSTR;   // 110592 B
    constexpr int SM_FC  = 3 * 384 * RSTR;   // 165888 B
    cudaFuncSetAttribute(persistent_rnn,
                         cudaFuncAttributeMaxDynamicSharedMemorySize, SM_RNN);
    cudaFuncSetAttribute(fc_gemm,
                         cudaFuncAttributeMaxDynamicSharedMemorySize, SM_FC);

    persistent_rnn<<<NCTA, 256, SM_RNN>>>(
        x_hi, x_lo, hid_hi, hid_lo,
        Wih_hi, Wih_lo, Whh_hi, Whh_lo,
        b_ih, b_hh,
        out_hi, out_lo, h0_hi, h0_lo);

    const dim3 fc_grid(MTOT / 128, Odim / 128);  // (128, 64)
    fc_gemm<<<fc_grid, 256, SM_FC>>>(
        out_hi, out_lo, fcW, fc_b, out);
}